// round 1
// baseline (speedup 1.0000x reference)
#include <cuda_runtime.h>
#include <cuda_bf16.h>
#include <math.h>

// Problem constants
#define BB   2
#define SS   2048
#define DIM  4096
#define NH   32
#define NKV  8
#define HD   128
#define NT   (BB*SS)          // 4096 tokens
#define QDIM (NH*HD)          // 4096
#define KDIM (NKV*HD)         // 1024

// ---------------- scratch (device globals; no allocation allowed) ----------
__device__ float g_Q[NT * QDIM];   // 64 MB
__device__ float g_K[NT * KDIM];   // 16 MB
__device__ float g_V[NT * KDIM];   // 16 MB
__device__ float g_A[NT * QDIM];   // 64 MB (attention output)

// ---------------- SGEMM: C[M,N] = A[M,K] * B[K,N], fp32, 128x128x8 tiles ---
// M,N multiples of 128; K multiple of 8. 256 threads, 8x8 per thread.
__global__ __launch_bounds__(256) void sgemm128(const float* __restrict__ A,
                                                const float* __restrict__ B,
                                                float* __restrict__ C,
                                                int M, int N, int K)
{
    __shared__ float As[8][128];   // transposed A tile
    __shared__ float Bs[8][128];

    const int tid = threadIdx.x;
    const int tx = tid % 16;
    const int ty = tid / 16;
    const int row0 = blockIdx.y * 128;
    const int col0 = blockIdx.x * 128;

    const int a_row = tid >> 1;          // 0..127
    const int a_col = (tid & 1) * 4;     // 0 or 4
    const int b_row = tid >> 5;          // 0..7
    const int b_col = (tid & 31) * 4;    // 0..124

    const float* Aptr = A + (size_t)(row0 + a_row) * K + a_col;
    const float* Bptr = B + (size_t)b_row * N + col0 + b_col;

    float acc[8][8];
#pragma unroll
    for (int i = 0; i < 8; i++)
#pragma unroll
        for (int j = 0; j < 8; j++) acc[i][j] = 0.f;

    for (int k0 = 0; k0 < K; k0 += 8) {
        float4 av = *(const float4*)(Aptr + k0);
        As[a_col + 0][a_row] = av.x;
        As[a_col + 1][a_row] = av.y;
        As[a_col + 2][a_row] = av.z;
        As[a_col + 3][a_row] = av.w;
        float4 bv = *(const float4*)(Bptr + (size_t)k0 * N);
        *(float4*)&Bs[b_row][b_col] = bv;
        __syncthreads();

#pragma unroll
        for (int k = 0; k < 8; k++) {
            float ar[8], br[8];
            *(float4*)&ar[0] = *(const float4*)&As[k][ty * 8];
            *(float4*)&ar[4] = *(const float4*)&As[k][ty * 8 + 4];
            *(float4*)&br[0] = *(const float4*)&Bs[k][tx * 8];
            *(float4*)&br[4] = *(const float4*)&Bs[k][tx * 8 + 4];
#pragma unroll
            for (int i = 0; i < 8; i++)
#pragma unroll
                for (int j = 0; j < 8; j++)
                    acc[i][j] = fmaf(ar[i], br[j], acc[i][j]);
        }
        __syncthreads();
    }

#pragma unroll
    for (int i = 0; i < 8; i++) {
        float* cp = C + (size_t)(row0 + ty * 8 + i) * N + col0 + tx * 8;
        float4 c0 = make_float4(acc[i][0], acc[i][1], acc[i][2], acc[i][3]);
        float4 c1 = make_float4(acc[i][4], acc[i][5], acc[i][6], acc[i][7]);
        *(float4*)(cp)     = c0;
        *(float4*)(cp + 4) = c1;
    }
}

// ---------------- RoPE: in-place on [NT][nHeads*128] ------------------------
__global__ void rope_kernel(float* __restrict__ X,
                            const float* __restrict__ cosT,
                            const float* __restrict__ sinT,
                            int nHeads)
{
    int idx = blockIdx.x * blockDim.x + threadIdx.x;  // pair index
    int total = NT * nHeads * 64;
    if (idx >= total) return;
    int d = idx & 63;
    int h = (idx >> 6) % nHeads;
    int t = idx / (64 * nHeads);
    int s = t & (SS - 1);   // token position within sequence

    float* p = X + (size_t)t * (nHeads * HD) + h * HD;
    float x1 = p[d];
    float x2 = p[d + 64];
    float c1 = cosT[s * HD + d];
    float s1 = sinT[s * HD + d];
    float c2 = cosT[s * HD + d + 64];
    float s2 = sinT[s * HD + d + 64];
    p[d]      = x1 * c1 - x2 * s1;
    p[d + 64] = x2 * c2 + x1 * s2;
}

// ---------------- Flash attention (fp32, causal, grouped heads) -------------
// grid.x = B*NH (64), grid.y = S/64 (32). 256 threads.
// smem: Qst[128][64] | Kst[128][64] | Vs[64][128] | Ss[64][65] | m/l/c[64each]
#define ATT_SMEM_FLOATS (128*64 + 128*64 + 64*128 + 64*65 + 3*64)

__global__ __launch_bounds__(256) void attn_kernel(const float* __restrict__ Q,
                                                   const float* __restrict__ K,
                                                   const float* __restrict__ V,
                                                   float* __restrict__ O)
{
    extern __shared__ float sm[];
    float* Qst  = sm;                       // [128][64] k-major
    float* Kst  = Qst + 128 * 64;           // [128][64] k-major
    float* Vs   = Kst + 128 * 64;           // [64][128]
    float* Ss   = Vs + 64 * 128;            // [64][65]
    float* mrow = Ss + 64 * 65;
    float* lrow = mrow + 64;
    float* crow = lrow + 64;

    const int bh = blockIdx.x;
    const int qb = blockIdx.y;
    const int b = bh >> 5;          // /32
    const int h = bh & 31;
    const int g = h >> 2;           // kv head = h/4
    const int tid = threadIdx.x;
    const int tx = tid % 16;
    const int ty = tid / 16;
    const int tok0 = b * SS + qb * 64;

    // Load Q tile transposed: Qst[k][r]
    for (int idx = tid * 4; idx < 64 * 128; idx += 1024) {
        int r = idx >> 7;
        int k = idx & 127;
        float4 v = *(const float4*)(Q + (size_t)(tok0 + r) * QDIM + h * HD + k);
        Qst[(k + 0) * 64 + r] = v.x;
        Qst[(k + 1) * 64 + r] = v.y;
        Qst[(k + 2) * 64 + r] = v.z;
        Qst[(k + 3) * 64 + r] = v.w;
    }
    if (tid < 64) { mrow[tid] = -1e30f; lrow[tid] = 0.f; }

    float o[4][8];
#pragma unroll
    for (int i = 0; i < 4; i++)
#pragma unroll
        for (int j = 0; j < 8; j++) o[i][j] = 0.f;

    __syncthreads();

    const float scale = 0.08838834764831845f;  // 1/sqrt(128)

    for (int kt = 0; kt <= qb; kt++) {
        // Load K (transposed) and V (natural) tiles
        for (int idx = tid * 4; idx < 64 * 128; idx += 1024) {
            int r = idx >> 7;
            int k = idx & 127;
            int tk = b * SS + kt * 64 + r;
            float4 kv = *(const float4*)(K + (size_t)tk * KDIM + g * HD + k);
            Kst[(k + 0) * 64 + r] = kv.x;
            Kst[(k + 1) * 64 + r] = kv.y;
            Kst[(k + 2) * 64 + r] = kv.z;
            Kst[(k + 3) * 64 + r] = kv.w;
            float4 vv = *(const float4*)(V + (size_t)tk * KDIM + g * HD + k);
            *(float4*)&Vs[r * 128 + k] = vv;
        }
        __syncthreads();

        // S = Q * K^T  (64x64), thread computes 4x4
        float sacc[4][4];
#pragma unroll
        for (int i = 0; i < 4; i++)
#pragma unroll
            for (int j = 0; j < 4; j++) sacc[i][j] = 0.f;

#pragma unroll 4
        for (int k = 0; k < 128; k++) {
            float4 qa = *(const float4*)&Qst[k * 64 + ty * 4];
            float4 kb = *(const float4*)&Kst[k * 64 + tx * 4];
            float qr[4] = {qa.x, qa.y, qa.z, qa.w};
            float kr[4] = {kb.x, kb.y, kb.z, kb.w};
#pragma unroll
            for (int i = 0; i < 4; i++)
#pragma unroll
                for (int j = 0; j < 4; j++)
                    sacc[i][j] = fmaf(qr[i], kr[j], sacc[i][j]);
        }

        const bool diag = (kt == qb);
#pragma unroll
        for (int i = 0; i < 4; i++) {
            int lr = ty * 4 + i;
#pragma unroll
            for (int j = 0; j < 4; j++) {
                int lc = tx * 4 + j;
                float v = sacc[i][j] * scale;
                if (diag && lc > lr) v = -1e30f;
                Ss[lr * 65 + lc] = v;
            }
        }
        __syncthreads();

        // Online softmax per row (64 threads active)
        if (tid < 64) {
            int r = tid;
            float m = mrow[r];
            float mx = m;
#pragma unroll 8
            for (int c = 0; c < 64; c++) mx = fmaxf(mx, Ss[r * 65 + c]);
            float corr = __expf(m - mx);
            float sum = 0.f;
#pragma unroll 8
            for (int c = 0; c < 64; c++) {
                float e = __expf(Ss[r * 65 + c] - mx);
                Ss[r * 65 + c] = e;
                sum += e;
            }
            mrow[r] = mx;
            lrow[r] = lrow[r] * corr + sum;
            crow[r] = corr;
        }
        __syncthreads();

        // Rescale O, then O += P * V. Thread tile: rows ty*4.., cols tx*8..
#pragma unroll
        for (int i = 0; i < 4; i++) {
            float cf = crow[ty * 4 + i];
#pragma unroll
            for (int j = 0; j < 8; j++) o[i][j] *= cf;
        }
#pragma unroll 2
        for (int kk = 0; kk < 64; kk++) {
            float4 v0 = *(const float4*)&Vs[kk * 128 + tx * 8];
            float4 v1 = *(const float4*)&Vs[kk * 128 + tx * 8 + 4];
            float vr[8] = {v0.x, v0.y, v0.z, v0.w, v1.x, v1.y, v1.z, v1.w};
            float p[4];
#pragma unroll
            for (int i = 0; i < 4; i++) p[i] = Ss[(ty * 4 + i) * 65 + kk];
#pragma unroll
            for (int i = 0; i < 4; i++)
#pragma unroll
                for (int j = 0; j < 8; j++)
                    o[i][j] = fmaf(p[i], vr[j], o[i][j]);
        }
        __syncthreads();
    }

    // Epilogue: normalize and write to [token][h*128 + c]
#pragma unroll
    for (int i = 0; i < 4; i++) {
        int r = ty * 4 + i;
        float inv = 1.f / lrow[r];
        float* op = O + (size_t)(tok0 + r) * QDIM + h * HD + tx * 8;
        float4 w0 = make_float4(o[i][0] * inv, o[i][1] * inv, o[i][2] * inv, o[i][3] * inv);
        float4 w1 = make_float4(o[i][4] * inv, o[i][5] * inv, o[i][6] * inv, o[i][7] * inv);
        *(float4*)(op)     = w0;
        *(float4*)(op + 4) = w1;
    }
}

// ---------------- launcher ---------------------------------------------------
extern "C" void kernel_launch(void* const* d_in, const int* in_sizes, int n_in,
                              void* d_out, int out_size)
{
    const float* x    = (const float*)d_in[0];
    const float* cosT = (const float*)d_in[1];
    const float* sinT = (const float*)d_in[2];
    const float* Wq   = (const float*)d_in[3];
    const float* Wk   = (const float*)d_in[4];
    const float* Wv   = (const float*)d_in[5];
    const float* Wo   = (const float*)d_in[6];
    float* out = (float*)d_out;

    float *Q, *K, *V, *A;
    cudaGetSymbolAddress((void**)&Q, g_Q);
    cudaGetSymbolAddress((void**)&K, g_K);
    cudaGetSymbolAddress((void**)&V, g_V);
    cudaGetSymbolAddress((void**)&A, g_A);

    // QKV projections
    sgemm128<<<dim3(QDIM / 128, NT / 128), 256>>>(x, Wq, Q, NT, QDIM, DIM);
    sgemm128<<<dim3(KDIM / 128, NT / 128), 256>>>(x, Wk, K, NT, KDIM, DIM);
    sgemm128<<<dim3(KDIM / 128, NT / 128), 256>>>(x, Wv, V, NT, KDIM, DIM);

    // RoPE
    {
        int totQ = NT * NH * 64;
        int totK = NT * NKV * 64;
        rope_kernel<<<(totQ + 255) / 256, 256>>>(Q, cosT, sinT, NH);
        rope_kernel<<<(totK + 255) / 256, 256>>>(K, cosT, sinT, NKV);
    }

    // Flash attention
    {
        size_t smem = ATT_SMEM_FLOATS * sizeof(float);
        cudaFuncSetAttribute(attn_kernel,
                             cudaFuncAttributeMaxDynamicSharedMemorySize,
                             (int)smem);
        attn_kernel<<<dim3(BB * NH, SS / 64), 256, smem>>>(Q, K, V, A);
    }

    // Output projection
    sgemm128<<<dim3(QDIM / 128, NT / 128), 256>>>(A, Wo, out, NT, QDIM, DIM);
}

// round 3
// speedup vs baseline: 1.7540x; 1.7540x over previous
#include <cuda_runtime.h>
#include <cuda_bf16.h>
#include <math.h>
#include <stdint.h>

// Problem constants
#define BB   2
#define SS   2048
#define DIM  4096
#define NH   32
#define NKV  8
#define HD   128
#define NT   (BB*SS)          // 4096 tokens
#define QDIM (NH*HD)          // 4096
#define KDIM (NKV*HD)         // 1024

// ---------------- scratch (device globals; no allocation allowed) ----------
__device__ float g_Q[NT * QDIM];
__device__ float g_K[NT * KDIM];
__device__ float g_V[NT * KDIM];
__device__ __nv_bfloat16 g_xh[NT * DIM];
__device__ __nv_bfloat16 g_xl[NT * DIM];
__device__ __nv_bfloat16 g_Wqh[QDIM * DIM];
__device__ __nv_bfloat16 g_Wql[QDIM * DIM];
__device__ __nv_bfloat16 g_Wkh[KDIM * DIM];
__device__ __nv_bfloat16 g_Wkl[KDIM * DIM];
__device__ __nv_bfloat16 g_Wvh[KDIM * DIM];
__device__ __nv_bfloat16 g_Wvl[KDIM * DIM];
__device__ __nv_bfloat16 g_Woh[DIM * QDIM];   // transposed: [N=DIM rows][K=QDIM]
__device__ __nv_bfloat16 g_Wol[DIM * QDIM];
__device__ __nv_bfloat16 g_Ah[NT * QDIM];     // attention out hi
__device__ __nv_bfloat16 g_Al[NT * QDIM];     // attention out lo

// ======================= PTX helpers =======================
__device__ __forceinline__ uint32_t smem_u32(const void* p) {
    uint32_t a;
    asm("{ .reg .u64 t; cvta.to.shared.u64 t, %1; cvt.u32.u64 %0, t; }" : "=r"(a) : "l"(p));
    return a;
}
__device__ __forceinline__ void cp_async16(uint32_t dst, const void* src) {
    asm volatile("cp.async.cg.shared.global [%0], [%1], 16;" :: "r"(dst), "l"(src));
}
#define CP_COMMIT() asm volatile("cp.async.commit_group;" ::: "memory")

__device__ __forceinline__ uint32_t sw128(uint32_t b) { return b ^ ((b >> 3) & 0x70); }

#define LDSM4(r, addr) \
    asm volatile("ldmatrix.sync.aligned.m8n8.x4.shared.b16 {%0,%1,%2,%3}, [%4];" \
        : "=r"((r)[0]), "=r"((r)[1]), "=r"((r)[2]), "=r"((r)[3]) : "r"(addr))

#define MMA16816(c, a, b0, b1) \
    asm volatile("mma.sync.aligned.m16n8k16.row.col.f32.bf16.bf16.f32 " \
        "{%0,%1,%2,%3}, {%4,%5,%6,%7}, {%8,%9}, {%0,%1,%2,%3};" \
        : "+f"((c)[0]), "+f"((c)[1]), "+f"((c)[2]), "+f"((c)[3]) \
        : "r"((a)[0]), "r"((a)[1]), "r"((a)[2]), "r"((a)[3]), "r"(b0), "r"(b1))

// =============== split-precision HMMA GEMM ===============
// C[M,N] = (Ah+Al)[M,K] * (Bh+Bl)^T, B tensors [N,K] row-major bf16.
// 3-term: Ah*Bh + Al*Bh + Ah*Bl, fp32 accumulation.
// CTA tile 128x128, BK=64, double-buffered cp.async, SW128 smem layout.
// smem per stage: 4 tiles (Ah,Al,Bh,Bl) x 128x64 bf16 (16KB) = 64KB.
#define GSMEM_BYTES (2 * 4 * 16384)

__device__ __forceinline__ void load_stage(
    uint32_t buf, const __nv_bfloat16* Ah, const __nv_bfloat16* Al,
    const __nv_bfloat16* Bh, const __nv_bfloat16* Bl,
    int row0, int col0, int K, int it, int tid)
{
    #pragma unroll 4
    for (int c = tid; c < 4096; c += 256) {
        const int t = c >> 10;            // 0:Ah 1:Al 2:Bh 3:Bl
        const int idx = c & 1023;
        const int r = idx >> 3;
        const int sg = idx & 7;
        const __nv_bfloat16* base = (t == 0) ? Ah : (t == 1) ? Al : (t == 2) ? Bh : Bl;
        const int grow = ((t < 2) ? row0 : col0) + r;
        const void* src = base + (size_t)grow * K + it * 64 + sg * 8;
        const uint32_t dst = buf + t * 16384 + sw128(r * 128 + sg * 16);
        cp_async16(dst, src);
    }
    CP_COMMIT();
}

__global__ __launch_bounds__(256) void gemm_bf16x3(
    const __nv_bfloat16* __restrict__ Ah, const __nv_bfloat16* __restrict__ Al,
    const __nv_bfloat16* __restrict__ Bh, const __nv_bfloat16* __restrict__ Bl,
    float* __restrict__ C, int M, int N, int K)
{
    extern __shared__ char smc[];
    const uint32_t sb = smem_u32(smc);
    const int tid = threadIdx.x;
    const int wid = tid >> 5;
    const int lane = tid & 31;
    const int row0 = blockIdx.y * 128;
    const int col0 = blockIdx.x * 128;

    const int wm0 = (wid >> 2) * 64;   // warp m offset within CTA tile
    const int wn0 = (wid & 3) * 32;    // warp n offset

    float acc[4][4][4];
    #pragma unroll
    for (int i = 0; i < 4; i++)
        #pragma unroll
        for (int j = 0; j < 4; j++)
            #pragma unroll
            for (int r = 0; r < 4; r++) acc[i][j][r] = 0.f;

    const int KT = K / 64;
    load_stage(sb, Ah, Al, Bh, Bl, row0, col0, K, 0, tid);

    for (int it = 0; it < KT; it++) {
        const uint32_t buf = sb + (it & 1) * 65536;
        if (it + 1 < KT) {
            load_stage(sb + ((it + 1) & 1) * 65536, Ah, Al, Bh, Bl, row0, col0, K, it + 1, tid);
            asm volatile("cp.async.wait_group 1;" ::: "memory");
        } else {
            asm volatile("cp.async.wait_group 0;" ::: "memory");
        }
        __syncthreads();

        const uint32_t aHb = buf;
        const uint32_t aLb = buf + 16384;
        const uint32_t bHb = buf + 32768;
        const uint32_t bLb = buf + 49152;

        #pragma unroll
        for (int k16 = 0; k16 < 4; k16++) {
            const int colb = k16 * 32 + (lane >> 4) * 16;
            uint32_t ah[4][4], al[4][4], bh[2][4], bl[2][4];
            #pragma unroll
            for (int mi = 0; mi < 4; mi++) {
                const uint32_t off = sw128((wm0 + mi * 16 + (lane & 15)) * 128 + colb);
                LDSM4(ah[mi], aHb + off);
                LDSM4(al[mi], aLb + off);
            }
            #pragma unroll
            for (int np = 0; np < 2; np++) {
                const uint32_t off = sw128((wn0 + np * 16 + (lane & 15)) * 128 + colb);
                LDSM4(bh[np], bHb + off);
                LDSM4(bl[np], bLb + off);
            }
            #pragma unroll
            for (int mi = 0; mi < 4; mi++) {
                #pragma unroll
                for (int nj = 0; nj < 4; nj++) {
                    const int np = nj >> 1, h = nj & 1;
                    MMA16816(acc[mi][nj], ah[mi], bh[np][h], bh[np][2 + h]);
                    MMA16816(acc[mi][nj], al[mi], bh[np][h], bh[np][2 + h]);
                    MMA16816(acc[mi][nj], ah[mi], bl[np][h], bl[np][2 + h]);
                }
            }
        }
        __syncthreads();
    }

    // epilogue: direct float2 stores
    #pragma unroll
    for (int mi = 0; mi < 4; mi++) {
        #pragma unroll
        for (int nj = 0; nj < 4; nj++) {
            const int row = row0 + wm0 + mi * 16 + (lane >> 2);
            const int col = col0 + wn0 + nj * 8 + (lane & 3) * 2;
            *(float2*)(C + (size_t)row * N + col)       = make_float2(acc[mi][nj][0], acc[mi][nj][1]);
            *(float2*)(C + (size_t)(row + 8) * N + col) = make_float2(acc[mi][nj][2], acc[mi][nj][3]);
        }
    }
}

// =============== fp32 -> bf16 hi/lo split (row-major) ===========
__global__ void split_rows(const float* __restrict__ X,
                           __nv_bfloat16* __restrict__ Xh,
                           __nv_bfloat16* __restrict__ Xl, int total4)
{
    int i = blockIdx.x * blockDim.x + threadIdx.x;
    if (i >= total4) return;
    float4 v = *(const float4*)(X + (size_t)i * 4);
    __nv_bfloat16 h[4], l[4];
    float vv[4] = {v.x, v.y, v.z, v.w};
    #pragma unroll
    for (int j = 0; j < 4; j++) {
        h[j] = __float2bfloat16(vv[j]);
        l[j] = __float2bfloat16(vv[j] - __bfloat162float(h[j]));
    }
    *(uint2*)(Xh + (size_t)i * 4) = *(uint2*)h;
    *(uint2*)(Xl + (size_t)i * 4) = *(uint2*)l;
}

// =============== transpose + split: W[K,N] fp32 -> T_hi/lo [N,K] bf16 ========
__global__ void transpose_split(const float* __restrict__ W,
                                __nv_bfloat16* __restrict__ Th,
                                __nv_bfloat16* __restrict__ Tl, int Kd, int Nd)
{
    __shared__ float t[32][33];
    const int n0 = blockIdx.x * 32, k0 = blockIdx.y * 32;
    const int tx = threadIdx.x, ty = threadIdx.y;
    t[ty][tx] = W[(size_t)(k0 + ty) * Nd + n0 + tx];
    __syncthreads();
    float v = t[tx][ty];  // W[k0+tx][n0+ty]
    __nv_bfloat16 hi = __float2bfloat16(v);
    float lo = v - __bfloat162float(hi);
    Th[(size_t)(n0 + ty) * Kd + k0 + tx] = hi;
    Tl[(size_t)(n0 + ty) * Kd + k0 + tx] = __float2bfloat16(lo);
}

// ---------------- RoPE: in-place on [NT][nHeads*128] ------------------------
__global__ void rope_kernel(float* __restrict__ X,
                            const float* __restrict__ cosT,
                            const float* __restrict__ sinT,
                            int nHeads)
{
    int idx = blockIdx.x * blockDim.x + threadIdx.x;
    int total = NT * nHeads * 64;
    if (idx >= total) return;
    int d = idx & 63;
    int h = (idx >> 6) % nHeads;
    int t = idx / (64 * nHeads);
    int s = t & (SS - 1);

    float* p = X + (size_t)t * (nHeads * HD) + h * HD;
    float x1 = p[d];
    float x2 = p[d + 64];
    float c1 = cosT[s * HD + d];
    float s1 = sinT[s * HD + d];
    float c2 = cosT[s * HD + d + 64];
    float s2 = sinT[s * HD + d + 64];
    p[d]      = x1 * c1 - x2 * s1;
    p[d + 64] = x2 * c2 + x1 * s2;
}

// ---------------- Flash attention (fp32, causal, grouped heads) -------------
#define ATT_SMEM_FLOATS (128*64 + 128*64 + 64*128 + 64*65 + 3*64)

__global__ __launch_bounds__(256) void attn_kernel(const float* __restrict__ Q,
                                                   const float* __restrict__ K,
                                                   const float* __restrict__ V,
                                                   __nv_bfloat16* __restrict__ Oh,
                                                   __nv_bfloat16* __restrict__ Ol)
{
    extern __shared__ float sm[];
    float* Qst  = sm;
    float* Kst  = Qst + 128 * 64;
    float* Vs   = Kst + 128 * 64;
    float* Ss   = Vs + 64 * 128;
    float* mrow = Ss + 64 * 65;
    float* lrow = mrow + 64;
    float* crow = lrow + 64;

    const int bh = blockIdx.x;
    const int qb = blockIdx.y;
    const int b = bh >> 5;
    const int h = bh & 31;
    const int g = h >> 2;
    const int tid = threadIdx.x;
    const int tx = tid % 16;
    const int ty = tid / 16;
    const int tok0 = b * SS + qb * 64;

    for (int idx = tid * 4; idx < 64 * 128; idx += 1024) {
        int r = idx >> 7;
        int k = idx & 127;
        float4 v = *(const float4*)(Q + (size_t)(tok0 + r) * QDIM + h * HD + k);
        Qst[(k + 0) * 64 + r] = v.x;
        Qst[(k + 1) * 64 + r] = v.y;
        Qst[(k + 2) * 64 + r] = v.z;
        Qst[(k + 3) * 64 + r] = v.w;
    }
    if (tid < 64) { mrow[tid] = -1e30f; lrow[tid] = 0.f; }

    float o[4][8];
#pragma unroll
    for (int i = 0; i < 4; i++)
#pragma unroll
        for (int j = 0; j < 8; j++) o[i][j] = 0.f;

    __syncthreads();

    const float scale = 0.08838834764831845f;

    for (int kt = 0; kt <= qb; kt++) {
        for (int idx = tid * 4; idx < 64 * 128; idx += 1024) {
            int r = idx >> 7;
            int k = idx & 127;
            int tk = b * SS + kt * 64 + r;
            float4 kv = *(const float4*)(K + (size_t)tk * KDIM + g * HD + k);
            Kst[(k + 0) * 64 + r] = kv.x;
            Kst[(k + 1) * 64 + r] = kv.y;
            Kst[(k + 2) * 64 + r] = kv.z;
            Kst[(k + 3) * 64 + r] = kv.w;
            float4 vv = *(const float4*)(V + (size_t)tk * KDIM + g * HD + k);
            *(float4*)&Vs[r * 128 + k] = vv;
        }
        __syncthreads();

        float sacc[4][4];
#pragma unroll
        for (int i = 0; i < 4; i++)
#pragma unroll
            for (int j = 0; j < 4; j++) sacc[i][j] = 0.f;

#pragma unroll 4
        for (int k = 0; k < 128; k++) {
            float4 qa = *(const float4*)&Qst[k * 64 + ty * 4];
            float4 kb = *(const float4*)&Kst[k * 64 + tx * 4];
            float qr[4] = {qa.x, qa.y, qa.z, qa.w};
            float kr[4] = {kb.x, kb.y, kb.z, kb.w};
#pragma unroll
            for (int i = 0; i < 4; i++)
#pragma unroll
                for (int j = 0; j < 4; j++)
                    sacc[i][j] = fmaf(qr[i], kr[j], sacc[i][j]);
        }

        const bool diag = (kt == qb);
#pragma unroll
        for (int i = 0; i < 4; i++) {
            int lr = ty * 4 + i;
#pragma unroll
            for (int j = 0; j < 4; j++) {
                int lc = tx * 4 + j;
                float v = sacc[i][j] * scale;
                if (diag && lc > lr) v = -1e30f;
                Ss[lr * 65 + lc] = v;
            }
        }
        __syncthreads();

        if (tid < 64) {
            int r = tid;
            float m = mrow[r];
            float mx = m;
#pragma unroll 8
            for (int c = 0; c < 64; c++) mx = fmaxf(mx, Ss[r * 65 + c]);
            float corr = __expf(m - mx);
            float sum = 0.f;
#pragma unroll 8
            for (int c = 0; c < 64; c++) {
                float e = __expf(Ss[r * 65 + c] - mx);
                Ss[r * 65 + c] = e;
                sum += e;
            }
            mrow[r] = mx;
            lrow[r] = lrow[r] * corr + sum;
            crow[r] = corr;
        }
        __syncthreads();

#pragma unroll
        for (int i = 0; i < 4; i++) {
            float cf = crow[ty * 4 + i];
#pragma unroll
            for (int j = 0; j < 8; j++) o[i][j] *= cf;
        }
#pragma unroll 2
        for (int kk = 0; kk < 64; kk++) {
            float4 v0 = *(const float4*)&Vs[kk * 128 + tx * 8];
            float4 v1 = *(const float4*)&Vs[kk * 128 + tx * 8 + 4];
            float vr[8] = {v0.x, v0.y, v0.z, v0.w, v1.x, v1.y, v1.z, v1.w};
            float p[4];
#pragma unroll
            for (int i = 0; i < 4; i++) p[i] = Ss[(ty * 4 + i) * 65 + kk];
#pragma unroll
            for (int i = 0; i < 4; i++)
#pragma unroll
                for (int j = 0; j < 8; j++)
                    o[i][j] = fmaf(p[i], vr[j], o[i][j]);
        }
        __syncthreads();
    }

    // epilogue: normalize, split to bf16 hi/lo for the Wo tensor-core GEMM
#pragma unroll
    for (int i = 0; i < 4; i++) {
        int r = ty * 4 + i;
        float inv = 1.f / lrow[r];
        __nv_bfloat16 hb[8], lb[8];
#pragma unroll
        for (int j = 0; j < 8; j++) {
            float v = o[i][j] * inv;
            hb[j] = __float2bfloat16(v);
            lb[j] = __float2bfloat16(v - __bfloat162float(hb[j]));
        }
        size_t off = (size_t)(tok0 + r) * QDIM + h * HD + tx * 8;
        *(uint4*)(Oh + off) = *(uint4*)hb;
        *(uint4*)(Ol + off) = *(uint4*)lb;
    }
}

// ---------------- launcher ---------------------------------------------------
extern "C" void kernel_launch(void* const* d_in, const int* in_sizes, int n_in,
                              void* d_out, int out_size)
{
    const float* x    = (const float*)d_in[0];
    const float* cosT = (const float*)d_in[1];
    const float* sinT = (const float*)d_in[2];
    const float* Wq   = (const float*)d_in[3];
    const float* Wk   = (const float*)d_in[4];
    const float* Wv   = (const float*)d_in[5];
    const float* Wo   = (const float*)d_in[6];
    float* out = (float*)d_out;

    float *Q, *K, *V;
    __nv_bfloat16 *xh, *xl, *Wqh, *Wql, *Wkh, *Wkl, *Wvh, *Wvl, *Woh, *Wol, *Ah, *Al;
    cudaGetSymbolAddress((void**)&Q, g_Q);
    cudaGetSymbolAddress((void**)&K, g_K);
    cudaGetSymbolAddress((void**)&V, g_V);
    cudaGetSymbolAddress((void**)&xh, g_xh);
    cudaGetSymbolAddress((void**)&xl, g_xl);
    cudaGetSymbolAddress((void**)&Wqh, g_Wqh);
    cudaGetSymbolAddress((void**)&Wql, g_Wql);
    cudaGetSymbolAddress((void**)&Wkh, g_Wkh);
    cudaGetSymbolAddress((void**)&Wkl, g_Wkl);
    cudaGetSymbolAddress((void**)&Wvh, g_Wvh);
    cudaGetSymbolAddress((void**)&Wvl, g_Wvl);
    cudaGetSymbolAddress((void**)&Woh, g_Woh);
    cudaGetSymbolAddress((void**)&Wol, g_Wol);
    cudaGetSymbolAddress((void**)&Ah, g_Ah);
    cudaGetSymbolAddress((void**)&Al, g_Al);

    cudaFuncSetAttribute(gemm_bf16x3, cudaFuncAttributeMaxDynamicSharedMemorySize, GSMEM_BYTES);

    // conversions
    split_rows<<<(NT * DIM / 4 + 255) / 256, 256>>>(x, xh, xl, NT * DIM / 4);
    transpose_split<<<dim3(QDIM / 32, DIM / 32), dim3(32, 32)>>>(Wq, Wqh, Wql, DIM, QDIM);
    transpose_split<<<dim3(KDIM / 32, DIM / 32), dim3(32, 32)>>>(Wk, Wkh, Wkl, DIM, KDIM);
    transpose_split<<<dim3(KDIM / 32, DIM / 32), dim3(32, 32)>>>(Wv, Wvh, Wvl, DIM, KDIM);
    transpose_split<<<dim3(DIM / 32, QDIM / 32), dim3(32, 32)>>>(Wo, Woh, Wol, QDIM, DIM);

    // QKV projections (HMMA)
    gemm_bf16x3<<<dim3(QDIM / 128, NT / 128), 256, GSMEM_BYTES>>>(xh, xl, Wqh, Wql, Q, NT, QDIM, DIM);
    gemm_bf16x3<<<dim3(KDIM / 128, NT / 128), 256, GSMEM_BYTES>>>(xh, xl, Wkh, Wkl, K, NT, KDIM, DIM);
    gemm_bf16x3<<<dim3(KDIM / 128, NT / 128), 256, GSMEM_BYTES>>>(xh, xl, Wvh, Wvl, V, NT, KDIM, DIM);

    // RoPE
    {
        int totQ = NT * NH * 64;
        int totK = NT * NKV * 64;
        rope_kernel<<<(totQ + 255) / 256, 256>>>(Q, cosT, sinT, NH);
        rope_kernel<<<(totK + 255) / 256, 256>>>(K, cosT, sinT, NKV);
    }

    // Flash attention (fp32 FMA; epilogue writes bf16 hi/lo)
    {
        size_t smem = ATT_SMEM_FLOATS * sizeof(float);
        cudaFuncSetAttribute(attn_kernel, cudaFuncAttributeMaxDynamicSharedMemorySize, (int)smem);
        attn_kernel<<<dim3(BB * NH, SS / 64), 256, smem>>>(Q, K, V, Ah, Al);
    }

    // Output projection (HMMA)
    gemm_bf16x3<<<dim3(DIM / 128, NT / 128), 256, GSMEM_BYTES>>>(Ah, Al, Woh, Wol, out, NT, DIM, QDIM);
}

// round 5
// speedup vs baseline: 2.8121x; 1.6033x over previous
#include <cuda_runtime.h>
#include <cuda_bf16.h>
#include <math.h>
#include <stdint.h>

// Problem constants
#define BB   2
#define SS   2048
#define DIM  4096
#define NH   32
#define NKV  8
#define HD   128
#define NT   (BB*SS)          // 4096 tokens
#define QDIM (NH*HD)          // 4096
#define KDIM (NKV*HD)         // 1024

// ---------------- scratch (device globals; no allocation allowed) ----------
__device__ float g_Q[NT * QDIM];
__device__ float g_K[NT * KDIM];
__device__ float g_V[NT * KDIM];
__device__ __nv_bfloat16 g_xh[NT * DIM];
__device__ __nv_bfloat16 g_xl[NT * DIM];
__device__ __nv_bfloat16 g_Wqh[QDIM * DIM];
__device__ __nv_bfloat16 g_Wql[QDIM * DIM];
__device__ __nv_bfloat16 g_Wkh[KDIM * DIM];
__device__ __nv_bfloat16 g_Wkl[KDIM * DIM];
__device__ __nv_bfloat16 g_Wvh[KDIM * DIM];
__device__ __nv_bfloat16 g_Wvl[KDIM * DIM];
__device__ __nv_bfloat16 g_Woh[DIM * QDIM];   // transposed: [N=DIM rows][K=QDIM]
__device__ __nv_bfloat16 g_Wol[DIM * QDIM];
__device__ __nv_bfloat16 g_Ah[NT * QDIM];     // attention out hi
__device__ __nv_bfloat16 g_Al[NT * QDIM];     // attention out lo
// bf16 attention operands
__device__ __nv_bfloat16 g_Qh[NT * QDIM];
__device__ __nv_bfloat16 g_Ql[NT * QDIM];
__device__ __nv_bfloat16 g_Kh[NT * KDIM];
__device__ __nv_bfloat16 g_Kl[NT * KDIM];
__device__ __nv_bfloat16 g_Vth[BB * NKV * HD * SS];  // [b][g][d][s]
__device__ __nv_bfloat16 g_Vtl[BB * NKV * HD * SS];

// ======================= PTX helpers =======================
__device__ __forceinline__ uint32_t smem_u32(const void* p) {
    uint32_t a;
    asm("{ .reg .u64 t; cvta.to.shared.u64 t, %1; cvt.u32.u64 %0, t; }" : "=r"(a) : "l"(p));
    return a;
}
__device__ __forceinline__ void cp_async16(uint32_t dst, const void* src) {
    asm volatile("cp.async.cg.shared.global [%0], [%1], 16;" :: "r"(dst), "l"(src));
}
#define CP_COMMIT() asm volatile("cp.async.commit_group;" ::: "memory")

__device__ __forceinline__ uint32_t sw128(uint32_t b) { return b ^ ((b >> 3) & 0x70); }

__device__ __forceinline__ float exp2a(float x) {
    float r;
    asm("ex2.approx.f32 %0, %1;" : "=f"(r) : "f"(x));
    return r;
}

#define LDSM4(r, addr) \
    asm volatile("ldmatrix.sync.aligned.m8n8.x4.shared.b16 {%0,%1,%2,%3}, [%4];" \
        : "=r"((r)[0]), "=r"((r)[1]), "=r"((r)[2]), "=r"((r)[3]) : "r"(addr))

#define MMA16816(c, a, b0, b1) \
    asm volatile("mma.sync.aligned.m16n8k16.row.col.f32.bf16.bf16.f32 " \
        "{%0,%1,%2,%3}, {%4,%5,%6,%7}, {%8,%9}, {%0,%1,%2,%3};" \
        : "+f"((c)[0]), "+f"((c)[1]), "+f"((c)[2]), "+f"((c)[3]) \
        : "r"((a)[0]), "r"((a)[1]), "r"((a)[2]), "r"((a)[3]), "r"(b0), "r"(b1))

// =============== split-precision HMMA GEMM ===============
#define GSMEM_BYTES (2 * 4 * 16384)

__device__ __forceinline__ void load_stage(
    uint32_t buf, const __nv_bfloat16* Ah, const __nv_bfloat16* Al,
    const __nv_bfloat16* Bh, const __nv_bfloat16* Bl,
    int row0, int col0, int K, int it, int tid)
{
    #pragma unroll 4
    for (int c = tid; c < 4096; c += 256) {
        const int t = c >> 10;            // 0:Ah 1:Al 2:Bh 3:Bl
        const int idx = c & 1023;
        const int r = idx >> 3;
        const int sg = idx & 7;
        const __nv_bfloat16* base = (t == 0) ? Ah : (t == 1) ? Al : (t == 2) ? Bh : Bl;
        const int grow = ((t < 2) ? row0 : col0) + r;
        const void* src = base + (size_t)grow * K + it * 64 + sg * 8;
        const uint32_t dst = buf + t * 16384 + sw128(r * 128 + sg * 16);
        cp_async16(dst, src);
    }
    CP_COMMIT();
}

__global__ __launch_bounds__(256) void gemm_bf16x3(
    const __nv_bfloat16* __restrict__ Ah, const __nv_bfloat16* __restrict__ Al,
    const __nv_bfloat16* __restrict__ Bh, const __nv_bfloat16* __restrict__ Bl,
    float* __restrict__ C, int M, int N, int K)
{
    extern __shared__ char smc[];
    const uint32_t sb = smem_u32(smc);
    const int tid = threadIdx.x;
    const int wid = tid >> 5;
    const int lane = tid & 31;
    const int row0 = blockIdx.y * 128;
    const int col0 = blockIdx.x * 128;

    const int wm0 = (wid >> 2) * 64;
    const int wn0 = (wid & 3) * 32;

    float acc[4][4][4];
    #pragma unroll
    for (int i = 0; i < 4; i++)
        #pragma unroll
        for (int j = 0; j < 4; j++)
            #pragma unroll
            for (int r = 0; r < 4; r++) acc[i][j][r] = 0.f;

    const int KT = K / 64;
    load_stage(sb, Ah, Al, Bh, Bl, row0, col0, K, 0, tid);

    for (int it = 0; it < KT; it++) {
        const uint32_t buf = sb + (it & 1) * 65536;
        if (it + 1 < KT) {
            load_stage(sb + ((it + 1) & 1) * 65536, Ah, Al, Bh, Bl, row0, col0, K, it + 1, tid);
            asm volatile("cp.async.wait_group 1;" ::: "memory");
        } else {
            asm volatile("cp.async.wait_group 0;" ::: "memory");
        }
        __syncthreads();

        const uint32_t aHb = buf;
        const uint32_t aLb = buf + 16384;
        const uint32_t bHb = buf + 32768;
        const uint32_t bLb = buf + 49152;

        #pragma unroll
        for (int k16 = 0; k16 < 4; k16++) {
            const int colb = k16 * 32 + (lane >> 4) * 16;
            uint32_t ah[4][4], al[4][4], bh[2][4], bl[2][4];
            #pragma unroll
            for (int mi = 0; mi < 4; mi++) {
                const uint32_t off = sw128((wm0 + mi * 16 + (lane & 15)) * 128 + colb);
                LDSM4(ah[mi], aHb + off);
                LDSM4(al[mi], aLb + off);
            }
            #pragma unroll
            for (int np = 0; np < 2; np++) {
                const uint32_t off = sw128((wn0 + np * 16 + (lane & 15)) * 128 + colb);
                LDSM4(bh[np], bHb + off);
                LDSM4(bl[np], bLb + off);
            }
            #pragma unroll
            for (int mi = 0; mi < 4; mi++)
                #pragma unroll
                for (int nj = 0; nj < 4; nj++) {
                    const int np = nj >> 1, h = nj & 1;
                    MMA16816(acc[mi][nj], ah[mi], bh[np][h], bh[np][2 + h]);
                }
            #pragma unroll
            for (int mi = 0; mi < 4; mi++)
                #pragma unroll
                for (int nj = 0; nj < 4; nj++) {
                    const int np = nj >> 1, h = nj & 1;
                    MMA16816(acc[mi][nj], al[mi], bh[np][h], bh[np][2 + h]);
                }
            #pragma unroll
            for (int mi = 0; mi < 4; mi++)
                #pragma unroll
                for (int nj = 0; nj < 4; nj++) {
                    const int np = nj >> 1, h = nj & 1;
                    MMA16816(acc[mi][nj], ah[mi], bl[np][h], bl[np][2 + h]);
                }
        }
        __syncthreads();
    }

    #pragma unroll
    for (int mi = 0; mi < 4; mi++) {
        #pragma unroll
        for (int nj = 0; nj < 4; nj++) {
            const int row = row0 + wm0 + mi * 16 + (lane >> 2);
            const int col = col0 + wn0 + nj * 8 + (lane & 3) * 2;
            *(float2*)(C + (size_t)row * N + col)       = make_float2(acc[mi][nj][0], acc[mi][nj][1]);
            *(float2*)(C + (size_t)(row + 8) * N + col) = make_float2(acc[mi][nj][2], acc[mi][nj][3]);
        }
    }
}

// =============== fp32 -> bf16 hi/lo split (row-major) ===========
__global__ void split_rows(const float* __restrict__ X,
                           __nv_bfloat16* __restrict__ Xh,
                           __nv_bfloat16* __restrict__ Xl, int total4)
{
    int i = blockIdx.x * blockDim.x + threadIdx.x;
    if (i >= total4) return;
    float4 v = *(const float4*)(X + (size_t)i * 4);
    __nv_bfloat16 h[4], l[4];
    float vv[4] = {v.x, v.y, v.z, v.w};
    #pragma unroll
    for (int j = 0; j < 4; j++) {
        h[j] = __float2bfloat16(vv[j]);
        l[j] = __float2bfloat16(vv[j] - __bfloat162float(h[j]));
    }
    *(uint2*)(Xh + (size_t)i * 4) = *(uint2*)h;
    *(uint2*)(Xl + (size_t)i * 4) = *(uint2*)l;
}

// =============== transpose + split: W[K,N] fp32 -> T_hi/lo [N,K] bf16 ========
__global__ void transpose_split(const float* __restrict__ W,
                                __nv_bfloat16* __restrict__ Th,
                                __nv_bfloat16* __restrict__ Tl, int Kd, int Nd)
{
    __shared__ float t[32][33];
    const int n0 = blockIdx.x * 32, k0 = blockIdx.y * 32;
    const int tx = threadIdx.x, ty = threadIdx.y;
    t[ty][tx] = W[(size_t)(k0 + ty) * Nd + n0 + tx];
    __syncthreads();
    float v = t[tx][ty];
    __nv_bfloat16 hi = __float2bfloat16(v);
    float lo = v - __bfloat162float(hi);
    Th[(size_t)(n0 + ty) * Kd + k0 + tx] = hi;
    Tl[(size_t)(n0 + ty) * Kd + k0 + tx] = __float2bfloat16(lo);
}

// =============== RoPE + bf16 hi/lo split =====================================
__global__ void rope_split(const float* __restrict__ X,
                           const float* __restrict__ cosT,
                           const float* __restrict__ sinT,
                           __nv_bfloat16* __restrict__ Xh,
                           __nv_bfloat16* __restrict__ Xl, int nHeads)
{
    int idx = blockIdx.x * blockDim.x + threadIdx.x;
    int total = NT * nHeads * 32;
    if (idx >= total) return;
    int j = idx & 31;
    int hh = (idx >> 5) % nHeads;
    int t = idx / (32 * nHeads);
    int s = t & (SS - 1);
    int d = 2 * j;

    const float* p = X + (size_t)t * (nHeads * HD) + hh * HD;
    float x0 = p[d], x1 = p[d + 1], y0 = p[d + 64], y1 = p[d + 65];
    const float* cp = cosT + s * HD;
    const float* sp = sinT + s * HD;
    float r0 = x0 * cp[d]      - y0 * sp[d];
    float r1 = x1 * cp[d + 1]  - y1 * sp[d + 1];
    float r2 = y0 * cp[d + 64] + x0 * sp[d + 64];
    float r3 = y1 * cp[d + 65] + x1 * sp[d + 65];

    size_t o0 = (size_t)t * (nHeads * HD) + hh * HD + d;
    __nv_bfloat16 h0 = __float2bfloat16(r0), h1 = __float2bfloat16(r1);
    __nv_bfloat16 h2 = __float2bfloat16(r2), h3 = __float2bfloat16(r3);
    __nv_bfloat16 q0 = __float2bfloat16(r0 - __bfloat162float(h0));
    __nv_bfloat16 q1 = __float2bfloat16(r1 - __bfloat162float(h1));
    __nv_bfloat16 q2 = __float2bfloat16(r2 - __bfloat162float(h2));
    __nv_bfloat16 q3 = __float2bfloat16(r3 - __bfloat162float(h3));
    __nv_bfloat16 hp[2] = {h0, h1}; *(uint32_t*)(Xh + o0) = *(uint32_t*)hp;
    __nv_bfloat16 lp[2] = {q0, q1}; *(uint32_t*)(Xl + o0) = *(uint32_t*)lp;
    __nv_bfloat16 hp2[2] = {h2, h3}; *(uint32_t*)(Xh + o0 + 64) = *(uint32_t*)hp2;
    __nv_bfloat16 lp2[2] = {q2, q3}; *(uint32_t*)(Xl + o0 + 64) = *(uint32_t*)lp2;
}

// =============== V: fp32 [NT][KDIM] -> transposed bf16 hi/lo [b][g][d][s] ====
__global__ void v_split_t(const float* __restrict__ V,
                          __nv_bfloat16* __restrict__ Vth,
                          __nv_bfloat16* __restrict__ Vtl)
{
    __shared__ float t[32][33];
    const int c0 = blockIdx.x * 32;
    const int r0 = blockIdx.y * 32;
    const int tx = threadIdx.x, ty = threadIdx.y;
    t[ty][tx] = V[(size_t)(r0 + ty) * KDIM + c0 + tx];
    __syncthreads();
    float v = t[tx][ty];              // V[r0+tx][c0+ty]
    int tok = r0 + tx;
    int b = tok >> 11;
    int s = tok & (SS - 1);
    int col = c0 + ty;
    int g = col >> 7;
    int d = col & 127;
    size_t oidx = ((size_t)((b * NKV + g) * HD) + d) * SS + s;
    __nv_bfloat16 hi = __float2bfloat16(v);
    Vth[oidx] = hi;
    Vtl[oidx] = __float2bfloat16(v - __bfloat162float(hi));
}

// ---------------- HMMA flash attention (3-term split, causal, GQA) ----------
#define ASMEM_BYTES (196608)

__device__ __forceinline__ void attn_load_kv(
    uint32_t st, const __nv_bfloat16* Kh, const __nv_bfloat16* Kl,
    const __nv_bfloat16* Vth, const __nv_bfloat16* Vtl,
    int b, int g, int kt, int tid)
{
    const int tk0 = b * SS + kt * 64;
    #pragma unroll 4
    for (int c = tid; c < 2048; c += 256) {
        int hl = c >> 10, cc = c & 1023;
        int r = cc >> 4, sg = cc & 15, half = sg >> 3, sgi = sg & 7;
        const __nv_bfloat16* base = hl ? Kl : Kh;
        const void* src = base + (size_t)(tk0 + r) * KDIM + g * HD + half * 64 + sgi * 8;
        uint32_t dst = st + hl * 16384 + half * 8192 + sw128(r * 128 + sgi * 16);
        cp_async16(dst, src);
    }
    const size_t vrow0 = (size_t)((b * NKV + g) * HD) * SS;
    #pragma unroll 4
    for (int c = tid; c < 2048; c += 256) {
        int hl = c >> 10, cc = c & 1023;
        int d = cc >> 3, sg = cc & 7;
        const __nv_bfloat16* base = hl ? Vtl : Vth;
        const void* src = base + vrow0 + (size_t)d * SS + kt * 64 + sg * 8;
        uint32_t dst = st + 32768 + hl * 16384 + sw128(d * 128 + sg * 16);
        cp_async16(dst, src);
    }
    CP_COMMIT();
}

__global__ __launch_bounds__(256, 1) void attn_mma(
    const __nv_bfloat16* __restrict__ Qh, const __nv_bfloat16* __restrict__ Ql,
    const __nv_bfloat16* __restrict__ Kh, const __nv_bfloat16* __restrict__ Kl,
    const __nv_bfloat16* __restrict__ Vth, const __nv_bfloat16* __restrict__ Vtl,
    __nv_bfloat16* __restrict__ Oh, __nv_bfloat16* __restrict__ Ol)
{
    extern __shared__ char smc[];
    const uint32_t sb = smem_u32(smc);
    const int tid = threadIdx.x, wid = tid >> 5, lane = tid & 31;
    const int bid = blockIdx.x;
    const int qb = 15 - (bid >> 6);     // heavy-first
    const int bh = bid & 63;
    const int b = bh >> 5, h = bh & 31, g = h >> 2;
    const int tok0 = b * SS + qb * 128;
    const int KT = 2 * qb + 2;
    const float SCL = 0.08838834764831845f * 1.4426950408889634f;

    // Q load: hi/lo x 128 rows x 16 chunks(8 bf16) = 4096 chunks  [FIXED]
    #pragma unroll 4
    for (int c = tid; c < 4096; c += 256) {
        int hl = c >> 11, cc = c & 2047;
        int r = cc >> 4, sg = cc & 15, half = sg >> 3, sgi = sg & 7;
        const __nv_bfloat16* base = hl ? Ql : Qh;
        const void* src = base + (size_t)(tok0 + r) * QDIM + h * HD + half * 64 + sgi * 8;
        uint32_t dst = sb + hl * 32768 + half * 16384 + sw128(r * 128 + sgi * 16);
        cp_async16(dst, src);
    }
    attn_load_kv(sb + 65536, Kh, Kl, Vth, Vtl, b, g, 0, tid);

    float o[16][4];
    #pragma unroll
    for (int nd = 0; nd < 16; nd++)
        #pragma unroll
        for (int e = 0; e < 4; e++) o[nd][e] = 0.f;
    float m0 = -1e30f, m1 = -1e30f, l0 = 0.f, l1 = 0.f;

    const int qg0 = qb * 128 + wid * 16 + (lane >> 2);
    const int qg1 = qg0 + 8;

    for (int kt = 0; kt < KT; kt++) {
        if (kt + 1 < KT) {
            attn_load_kv(sb + 65536 + ((kt + 1) & 1) * 65536, Kh, Kl, Vth, Vtl, b, g, kt + 1, tid);
            asm volatile("cp.async.wait_group 1;" ::: "memory");
        } else {
            asm volatile("cp.async.wait_group 0;" ::: "memory");
        }
        __syncthreads();

        const uint32_t st = sb + 65536 + (kt & 1) * 65536;
        const bool skip = kt * 64 > qb * 128 + wid * 16 + 15;

        if (!skip) {
            float s[8][4];
            #pragma unroll
            for (int nj = 0; nj < 8; nj++)
                #pragma unroll
                for (int e = 0; e < 4; e++) s[nj][e] = 0.f;

            #pragma unroll
            for (int k16 = 0; k16 < 8; k16++) {
                const int half = k16 >> 2;
                const int cb = (k16 & 3) * 32 + (lane >> 4) * 16;
                const uint32_t qoff = sw128((wid * 16 + (lane & 15)) * 128 + cb);
                uint32_t ah[4], al[4];
                LDSM4(ah, sb + half * 16384 + qoff);
                LDSM4(al, sb + 32768 + half * 16384 + qoff);
                uint32_t bhf[4][4], blf[4][4];
                #pragma unroll
                for (int c = 0; c < 4; c++) {
                    const uint32_t koff = sw128((c * 16 + (lane & 15)) * 128 + cb);
                    LDSM4(bhf[c], st + half * 8192 + koff);
                    LDSM4(blf[c], st + 16384 + half * 8192 + koff);
                }
                #pragma unroll
                for (int nj = 0; nj < 8; nj++) {
                    const int np = nj >> 1, h2 = nj & 1;
                    MMA16816(s[nj], ah, bhf[np][h2], bhf[np][2 + h2]);
                }
                #pragma unroll
                for (int nj = 0; nj < 8; nj++) {
                    const int np = nj >> 1, h2 = nj & 1;
                    MMA16816(s[nj], al, bhf[np][h2], bhf[np][2 + h2]);
                }
                #pragma unroll
                for (int nj = 0; nj < 8; nj++) {
                    const int np = nj >> 1, h2 = nj & 1;
                    MMA16816(s[nj], ah, blf[np][h2], blf[np][2 + h2]);
                }
            }

            const bool domask = (kt * 64 + 63) > qg0;
            #pragma unroll
            for (int nj = 0; nj < 8; nj++) {
                #pragma unroll
                for (int e = 0; e < 4; e++) s[nj][e] *= SCL;
                if (domask) {
                    const int kc = kt * 64 + nj * 8 + (lane & 3) * 2;
                    if (kc     > qg0) s[nj][0] = -1e30f;
                    if (kc + 1 > qg0) s[nj][1] = -1e30f;
                    if (kc     > qg1) s[nj][2] = -1e30f;
                    if (kc + 1 > qg1) s[nj][3] = -1e30f;
                }
            }
            float mx0 = -1e30f, mx1 = -1e30f;
            #pragma unroll
            for (int nj = 0; nj < 8; nj++) {
                mx0 = fmaxf(mx0, fmaxf(s[nj][0], s[nj][1]));
                mx1 = fmaxf(mx1, fmaxf(s[nj][2], s[nj][3]));
            }
            mx0 = fmaxf(mx0, __shfl_xor_sync(0xffffffffu, mx0, 1));
            mx0 = fmaxf(mx0, __shfl_xor_sync(0xffffffffu, mx0, 2));
            mx1 = fmaxf(mx1, __shfl_xor_sync(0xffffffffu, mx1, 1));
            mx1 = fmaxf(mx1, __shfl_xor_sync(0xffffffffu, mx1, 2));
            const float nm0 = fmaxf(m0, mx0), nm1 = fmaxf(m1, mx1);
            const float c0 = exp2a(m0 - nm0), c1 = exp2a(m1 - nm1);
            float rs0 = 0.f, rs1 = 0.f;
            #pragma unroll
            for (int nj = 0; nj < 8; nj++) {
                s[nj][0] = exp2a(s[nj][0] - nm0);
                s[nj][1] = exp2a(s[nj][1] - nm0);
                s[nj][2] = exp2a(s[nj][2] - nm1);
                s[nj][3] = exp2a(s[nj][3] - nm1);
                rs0 += s[nj][0] + s[nj][1];
                rs1 += s[nj][2] + s[nj][3];
            }
            rs0 += __shfl_xor_sync(0xffffffffu, rs0, 1);
            rs0 += __shfl_xor_sync(0xffffffffu, rs0, 2);
            rs1 += __shfl_xor_sync(0xffffffffu, rs1, 1);
            rs1 += __shfl_xor_sync(0xffffffffu, rs1, 2);
            m0 = nm0; m1 = nm1;
            l0 = l0 * c0 + rs0;
            l1 = l1 * c1 + rs1;
            #pragma unroll
            for (int nd = 0; nd < 16; nd++) {
                o[nd][0] *= c0; o[nd][1] *= c0;
                o[nd][2] *= c1; o[nd][3] *= c1;
            }

            // P*V: P hi/lo packed in registers (C-frag -> A-frag)
            #pragma unroll
            for (int j2 = 0; j2 < 4; j2++) {
                const int n0 = 2 * j2, n1 = 2 * j2 + 1;
                uint32_t aPh[4], aPl[4];
                __nv_bfloat162 t0 = __floats2bfloat162_rn(s[n0][0], s[n0][1]);
                __nv_bfloat162 t1 = __floats2bfloat162_rn(s[n0][2], s[n0][3]);
                __nv_bfloat162 t2 = __floats2bfloat162_rn(s[n1][0], s[n1][1]);
                __nv_bfloat162 t3 = __floats2bfloat162_rn(s[n1][2], s[n1][3]);
                aPh[0] = *(uint32_t*)&t0; aPh[1] = *(uint32_t*)&t1;
                aPh[2] = *(uint32_t*)&t2; aPh[3] = *(uint32_t*)&t3;
                __nv_bfloat162 u0 = __floats2bfloat162_rn(s[n0][0] - __bfloat162float(t0.x),
                                                          s[n0][1] - __bfloat162float(t0.y));
                __nv_bfloat162 u1 = __floats2bfloat162_rn(s[n0][2] - __bfloat162float(t1.x),
                                                          s[n0][3] - __bfloat162float(t1.y));
                __nv_bfloat162 u2 = __floats2bfloat162_rn(s[n1][0] - __bfloat162float(t2.x),
                                                          s[n1][1] - __bfloat162float(t2.y));
                __nv_bfloat162 u3 = __floats2bfloat162_rn(s[n1][2] - __bfloat162float(t3.x),
                                                          s[n1][3] - __bfloat162float(t3.y));
                aPl[0] = *(uint32_t*)&u0; aPl[1] = *(uint32_t*)&u1;
                aPl[2] = *(uint32_t*)&u2; aPl[3] = *(uint32_t*)&u3;

                #pragma unroll
                for (int c = 0; c < 8; c++) {
                    const uint32_t voff = sw128((c * 16 + (lane & 15)) * 128 + j2 * 32 + (lane >> 4) * 16);
                    uint32_t vh[4], vl[4];
                    LDSM4(vh, st + 32768 + voff);
                    LDSM4(vl, st + 49152 + voff);
                    MMA16816(o[2 * c],     aPh, vh[0], vh[2]);
                    MMA16816(o[2 * c + 1], aPh, vh[1], vh[3]);
                    MMA16816(o[2 * c],     aPl, vh[0], vh[2]);
                    MMA16816(o[2 * c + 1], aPl, vh[1], vh[3]);
                    MMA16816(o[2 * c],     aPh, vl[0], vl[2]);
                    MMA16816(o[2 * c + 1], aPh, vl[1], vl[3]);
                }
            }
        }
        __syncthreads();
    }

    const float il0 = 1.f / l0, il1 = 1.f / l1;
    const int row0g = tok0 + wid * 16 + (lane >> 2);
    #pragma unroll
    for (int nd = 0; nd < 16; nd++) {
        const int col = h * HD + nd * 8 + (lane & 3) * 2;
        float v00 = o[nd][0] * il0, v01 = o[nd][1] * il0;
        float v10 = o[nd][2] * il1, v11 = o[nd][3] * il1;
        __nv_bfloat162 h0 = __floats2bfloat162_rn(v00, v01);
        __nv_bfloat162 h1 = __floats2bfloat162_rn(v10, v11);
        __nv_bfloat162 q0 = __floats2bfloat162_rn(v00 - __bfloat162float(h0.x),
                                                  v01 - __bfloat162float(h0.y));
        __nv_bfloat162 q1 = __floats2bfloat162_rn(v10 - __bfloat162float(h1.x),
                                                  v11 - __bfloat162float(h1.y));
        *(uint32_t*)(Oh + (size_t)row0g * QDIM + col)       = *(uint32_t*)&h0;
        *(uint32_t*)(Ol + (size_t)row0g * QDIM + col)       = *(uint32_t*)&q0;
        *(uint32_t*)(Oh + (size_t)(row0g + 8) * QDIM + col) = *(uint32_t*)&h1;
        *(uint32_t*)(Ol + (size_t)(row0g + 8) * QDIM + col) = *(uint32_t*)&q1;
    }
}

// ---------------- launcher ---------------------------------------------------
extern "C" void kernel_launch(void* const* d_in, const int* in_sizes, int n_in,
                              void* d_out, int out_size)
{
    const float* x    = (const float*)d_in[0];
    const float* cosT = (const float*)d_in[1];
    const float* sinT = (const float*)d_in[2];
    const float* Wq   = (const float*)d_in[3];
    const float* Wk   = (const float*)d_in[4];
    const float* Wv   = (const float*)d_in[5];
    const float* Wo   = (const float*)d_in[6];
    float* out = (float*)d_out;

    float *Q, *K, *V;
    __nv_bfloat16 *xh, *xl, *Wqh, *Wql, *Wkh, *Wkl, *Wvh, *Wvl, *Woh, *Wol, *Ah, *Al;
    __nv_bfloat16 *Qh, *Ql, *Khb, *Klb, *Vth, *Vtl;
    cudaGetSymbolAddress((void**)&Q, g_Q);
    cudaGetSymbolAddress((void**)&K, g_K);
    cudaGetSymbolAddress((void**)&V, g_V);
    cudaGetSymbolAddress((void**)&xh, g_xh);
    cudaGetSymbolAddress((void**)&xl, g_xl);
    cudaGetSymbolAddress((void**)&Wqh, g_Wqh);
    cudaGetSymbolAddress((void**)&Wql, g_Wql);
    cudaGetSymbolAddress((void**)&Wkh, g_Wkh);
    cudaGetSymbolAddress((void**)&Wkl, g_Wkl);
    cudaGetSymbolAddress((void**)&Wvh, g_Wvh);
    cudaGetSymbolAddress((void**)&Wvl, g_Wvl);
    cudaGetSymbolAddress((void**)&Woh, g_Woh);
    cudaGetSymbolAddress((void**)&Wol, g_Wol);
    cudaGetSymbolAddress((void**)&Ah, g_Ah);
    cudaGetSymbolAddress((void**)&Al, g_Al);
    cudaGetSymbolAddress((void**)&Qh, g_Qh);
    cudaGetSymbolAddress((void**)&Ql, g_Ql);
    cudaGetSymbolAddress((void**)&Khb, g_Kh);
    cudaGetSymbolAddress((void**)&Klb, g_Kl);
    cudaGetSymbolAddress((void**)&Vth, g_Vth);
    cudaGetSymbolAddress((void**)&Vtl, g_Vtl);

    cudaFuncSetAttribute(gemm_bf16x3, cudaFuncAttributeMaxDynamicSharedMemorySize, GSMEM_BYTES);
    cudaFuncSetAttribute(attn_mma, cudaFuncAttributeMaxDynamicSharedMemorySize, ASMEM_BYTES);

    // conversions
    split_rows<<<(NT * DIM / 4 + 255) / 256, 256>>>(x, xh, xl, NT * DIM / 4);
    transpose_split<<<dim3(QDIM / 32, DIM / 32), dim3(32, 32)>>>(Wq, Wqh, Wql, DIM, QDIM);
    transpose_split<<<dim3(KDIM / 32, DIM / 32), dim3(32, 32)>>>(Wk, Wkh, Wkl, DIM, KDIM);
    transpose_split<<<dim3(KDIM / 32, DIM / 32), dim3(32, 32)>>>(Wv, Wvh, Wvl, DIM, KDIM);
    transpose_split<<<dim3(DIM / 32, QDIM / 32), dim3(32, 32)>>>(Wo, Woh, Wol, QDIM, DIM);

    // QKV projections (HMMA)
    gemm_bf16x3<<<dim3(QDIM / 128, NT / 128), 256, GSMEM_BYTES>>>(xh, xl, Wqh, Wql, Q, NT, QDIM, DIM);
    gemm_bf16x3<<<dim3(KDIM / 128, NT / 128), 256, GSMEM_BYTES>>>(xh, xl, Wkh, Wkl, K, NT, KDIM, DIM);
    gemm_bf16x3<<<dim3(KDIM / 128, NT / 128), 256, GSMEM_BYTES>>>(xh, xl, Wvh, Wvl, V, NT, KDIM, DIM);

    // RoPE + split to bf16 operands
    rope_split<<<(NT * NH * 32 + 255) / 256, 256>>>(Q, cosT, sinT, Qh, Ql, NH);
    rope_split<<<(NT * NKV * 32 + 255) / 256, 256>>>(K, cosT, sinT, Khb, Klb, NKV);
    v_split_t<<<dim3(KDIM / 32, NT / 32), dim3(32, 32)>>>(V, Vth, Vtl);

    // HMMA flash attention
    attn_mma<<<1024, 256, ASMEM_BYTES>>>(Qh, Ql, Khb, Klb, Vth, Vtl, Ah, Al);

    // Output projection (HMMA)
    gemm_bf16x3<<<dim3(DIM / 128, NT / 128), 256, GSMEM_BYTES>>>(Ah, Al, Woh, Wol, out, NT, DIM, QDIM);
}